// round 5
// baseline (speedup 1.0000x reference)
#include <cuda_runtime.h>

// AttentionBlock fused gate kernel — ILP=4 over 4 adjacent positions.
// Inputs: xatt[B*L*C], xsaut[B*L*C], W_act[C], b_act[1], W_saut[C], b_saut[1], W2[1], b2[1]
// Output: out[B*L] fp32.  B=64, L=16384, C=64 -> n_pos = 1,048,576 (n_quads = 262,144).
//
// 16 lanes handle positions (4k..4k+3): each lane front-batches 8 independent
// LDG.128 (4 per tensor, contiguous 1KB per tensor per group). 4-level shuffle
// reduction over the 16-lane group; lane 0 computes the epilogue and does a
// single float4 store.

#define NEG_SLOPE 0.3f

__global__ __launch_bounds__(256) void attn_gate_kernel(
    const float* __restrict__ xatt,
    const float* __restrict__ xsaut,
    const float* __restrict__ W_act,
    const float* __restrict__ b_act,
    const float* __restrict__ W_saut,
    const float* __restrict__ b_saut,
    const float* __restrict__ W2,
    const float* __restrict__ b2,
    float* __restrict__ out,
    int n_quads)
{
    const int gtid   = blockIdx.x * blockDim.x + threadIdx.x;
    const int quad   = gtid >> 4;
    const int lane16 = gtid & 15;
    if (quad >= n_quads) return;

    const float4 wa = __ldg(reinterpret_cast<const float4*>(W_act)  + lane16);
    const float4 ws = __ldg(reinterpret_cast<const float4*>(W_saut) + lane16);

    const float4* __restrict__ xa4 = reinterpret_cast<const float4*>(xatt);
    const float4* __restrict__ xs4 = reinterpret_cast<const float4*>(xsaut);
    const size_t base = (size_t)quad * 64 + lane16;   // 4 positions * 16 float4

    // 8 independent global loads, front-batched (MLP=8)
    const float4 a0 = __ldg(xa4 + base);
    const float4 a1 = __ldg(xa4 + base + 16);
    const float4 a2 = __ldg(xa4 + base + 32);
    const float4 a3 = __ldg(xa4 + base + 48);
    const float4 s0 = __ldg(xs4 + base);
    const float4 s1 = __ldg(xs4 + base + 16);
    const float4 s2 = __ldg(xs4 + base + 32);
    const float4 s3 = __ldg(xs4 + base + 48);

    float pa0 = a0.x * wa.x + a0.y * wa.y + a0.z * wa.z + a0.w * wa.w;
    float pa1 = a1.x * wa.x + a1.y * wa.y + a1.z * wa.z + a1.w * wa.w;
    float pa2 = a2.x * wa.x + a2.y * wa.y + a2.z * wa.z + a2.w * wa.w;
    float pa3 = a3.x * wa.x + a3.y * wa.y + a3.z * wa.z + a3.w * wa.w;
    float ps0 = s0.x * ws.x + s0.y * ws.y + s0.z * ws.z + s0.w * ws.w;
    float ps1 = s1.x * ws.x + s1.y * ws.y + s1.z * ws.z + s1.w * ws.w;
    float ps2 = s2.x * ws.x + s2.y * ws.y + s2.z * ws.z + s2.w * ws.w;
    float ps3 = s3.x * ws.x + s3.y * ws.y + s3.z * ws.z + s3.w * ws.w;

    #pragma unroll
    for (int off = 8; off > 0; off >>= 1) {
        pa0 += __shfl_xor_sync(0xFFFFFFFFu, pa0, off);
        ps0 += __shfl_xor_sync(0xFFFFFFFFu, ps0, off);
        pa1 += __shfl_xor_sync(0xFFFFFFFFu, pa1, off);
        ps1 += __shfl_xor_sync(0xFFFFFFFFu, ps1, off);
        pa2 += __shfl_xor_sync(0xFFFFFFFFu, pa2, off);
        ps2 += __shfl_xor_sync(0xFFFFFFFFu, ps2, off);
        pa3 += __shfl_xor_sync(0xFFFFFFFFu, pa3, off);
        ps3 += __shfl_xor_sync(0xFFFFFFFFu, ps3, off);
    }

    if (lane16 == 0) {
        const float ba = __ldg(b_act);
        const float bs = __ldg(b_saut);
        const float w2 = __ldg(W2);
        const float bb = __ldg(b2);

        float4 o;
        {
            const float xs = ps0 + bs;
            float h = (pa0 + ba) + xs;
            h = (h >= 0.0f) ? h : NEG_SLOPE * h;
            o.x = xs / (1.0f + __expf(-(h * w2 + bb)));
        }
        {
            const float xs = ps1 + bs;
            float h = (pa1 + ba) + xs;
            h = (h >= 0.0f) ? h : NEG_SLOPE * h;
            o.y = xs / (1.0f + __expf(-(h * w2 + bb)));
        }
        {
            const float xs = ps2 + bs;
            float h = (pa2 + ba) + xs;
            h = (h >= 0.0f) ? h : NEG_SLOPE * h;
            o.z = xs / (1.0f + __expf(-(h * w2 + bb)));
        }
        {
            const float xs = ps3 + bs;
            float h = (pa3 + ba) + xs;
            h = (h >= 0.0f) ? h : NEG_SLOPE * h;
            o.w = xs / (1.0f + __expf(-(h * w2 + bb)));
        }
        reinterpret_cast<float4*>(out)[quad] = o;
    }
}

extern "C" void kernel_launch(void* const* d_in, const int* in_sizes, int n_in,
                              void* d_out, int out_size)
{
    const float* xatt   = (const float*)d_in[0];
    const float* xsaut  = (const float*)d_in[1];
    const float* W_act  = (const float*)d_in[2];
    const float* b_act  = (const float*)d_in[3];
    const float* W_saut = (const float*)d_in[4];
    const float* b_saut = (const float*)d_in[5];
    const float* W2     = (const float*)d_in[6];
    const float* b2     = (const float*)d_in[7];
    float* out = (float*)d_out;

    const int n_quads = out_size / 4;        // 262,144
    const int threads = 256;
    const long long total_threads = (long long)n_quads * 16;
    const int blocks = (int)((total_threads + threads - 1) / threads);

    attn_gate_kernel<<<blocks, threads>>>(xatt, xsaut, W_act, b_act,
                                          W_saut, b_saut, W2, b2,
                                          out, n_quads);
}